// round 10
// baseline (speedup 1.0000x reference)
#include <cuda_runtime.h>
#include <cuda_fp16.h>
#include <cstdint>

#define N_NODES 50000
#define N_EDGES 800000
#define HID 128
#define N_GRAPHS 512
#define BUCKET 64            // max in-degree slots (P(deg>64) ~ 1e-18)
#define AP 136               // padded smem row stride in halves (conflict-free)

// ---------------- scratch (device globals) ------------------------------------
__device__ __half g_h[N_NODES * HID];    // post-GEMM buffer (fp16)
__device__ __half g_act[N_NODES * HID];  // post-aggregate activation (fp16)
__device__ int    g_cnt[N_NODES];        // in-degree counter == bucket cursor
__device__ float  g_dinv[N_NODES];
__device__ int    g_colsrc[N_NODES * BUCKET];  // bucketed CSR (12.8 MB)
__device__ int    g_start[N_GRAPHS + 1];       // graph -> first node (sorted batch)
// W fragments (fp16 m16n8k16 B-operand order): [jtile(16)*8+kstep(8)][lane(32)] = uint2
__device__ uint2  g_Wf1[16 * 8 * 32];
__device__ uint2  g_Wf2[16 * 8 * 32];

// ---------------- helpers ------------------------------------------------------
__device__ __forceinline__ void mma16(float* d, uint32_t a0, uint32_t a1,
                                      uint32_t a2, uint32_t a3,
                                      uint32_t b0, uint32_t b1) {
    asm volatile(
        "mma.sync.aligned.m16n8k16.row.col.f32.f16.f16.f32 "
        "{%0,%1,%2,%3}, {%4,%5,%6,%7}, {%8,%9}, {%0,%1,%2,%3};"
        : "+f"(d[0]), "+f"(d[1]), "+f"(d[2]), "+f"(d[3])
        : "r"(a0), "r"(a1), "r"(a2), "r"(a3), "r"(b0), "r"(b1));
}

__device__ __forceinline__ float4 h2f4(uint2 v) {
    __half2 a = *(__half2*)&v.x, b = *(__half2*)&v.y;
    float2 fa = __half22float2(a), fb = __half22float2(b);
    return make_float4(fa.x, fa.y, fb.x, fb.y);
}

// ---------------- graph prep --------------------------------------------------
__global__ void zero_k() {
    int i = blockIdx.x * blockDim.x + threadIdx.x;
    if (i < N_NODES) g_cnt[i] = 0;
    else if (i < N_NODES + N_GRAPHS + 1) g_start[i - N_NODES] = N_NODES;
}

// single-pass bucketed CSR build (4 edges per thread)
__global__ void fill_k(const int4* __restrict__ src4, const int4* __restrict__ dst4) {
    int e = blockIdx.x * blockDim.x + threadIdx.x;
    if (e >= N_EDGES / 4) return;
    int4 s = src4[e];
    int4 d = dst4[e];
    int p;
    p = atomicAdd(&g_cnt[d.x], 1); if (p < BUCKET) g_colsrc[d.x * BUCKET + p] = s.x;
    p = atomicAdd(&g_cnt[d.y], 1); if (p < BUCKET) g_colsrc[d.y * BUCKET + p] = s.y;
    p = atomicAdd(&g_cnt[d.z], 1); if (p < BUCKET) g_colsrc[d.z * BUCKET + p] = s.z;
    p = atomicAdd(&g_cnt[d.w], 1); if (p < BUCKET) g_colsrc[d.w * BUCKET + p] = s.w;
}

__global__ void dinv_k(const int* __restrict__ batch) {
    int i = blockIdx.x * blockDim.x + threadIdx.x;
    if (i < N_NODES) {
        g_dinv[i] = rsqrtf((float)(g_cnt[i] + 1));
        // graph boundary detection (batch is sorted)
        int b = batch[i];
        if (i == 0 || batch[i - 1] != b) atomicMin(&g_start[b], i);
    }
}

// suffix-min so empty graphs inherit the next start (513 entries, trivial)
__global__ void suffix_k() {
    for (int g = N_GRAPHS - 1; g >= 0; g--) {
        int a = g_start[g], b = g_start[g + 1];
        g_start[g] = a < b ? a : b;
    }
}

// pack W (fp32 [128][128] row-major) into fp16 B-fragments
__global__ void wpack_k(const float* __restrict__ W1, const float* __restrict__ W2) {
    int idx = blockIdx.x * 256 + threadIdx.x;   // 0..8191
    int mat = idx >> 12;
    int rem = idx & 4095;
    int j = rem >> 8, s = (rem >> 5) & 7, lane = rem & 31;
    const float* W = mat ? W2 : W1;
    int n = j * 8 + (lane >> 2);
    int k0 = s * 16 + (lane & 3) * 2;
    __half2 b0 = __floats2half2_rn(W[k0 * 128 + n], W[(k0 + 1) * 128 + n]);
    __half2 b1 = __floats2half2_rn(W[(k0 + 8) * 128 + n], W[(k0 + 9) * 128 + n]);
    uint2 v;
    v.x = *(unsigned*)&b0;
    v.y = *(unsigned*)&b1;
    (mat ? g_Wf2 : g_Wf1)[(j * 8 + s) * 32 + lane] = v;
}

// ---------------- fp16 GEMM core ------------------------------------------------
// Block 256 thr = 4 M-warps x 2 N-warps, tile 64x128, K=128 in 8 ksteps of 16.
__device__ __forceinline__ void gemm_main(const __half* sm, const uint2* __restrict__ Wf,
                                          int row0, int tid) {
    int warp = tid >> 5, lane = tid & 31;
    int wm = warp & 3, wn = warp >> 2;
    int g = lane >> 2, ck = lane & 3;
    int arow = wm * 16 + g;

    float acc[8][4];
    #pragma unroll
    for (int j = 0; j < 8; j++)
        #pragma unroll
        for (int c = 0; c < 4; c++) acc[j][c] = 0.f;

    #pragma unroll
    for (int s = 0; s < 8; s++) {
        int k0 = s * 16 + ck * 2;
        uint32_t a0 = *(const uint32_t*)&sm[arow * AP + k0];
        uint32_t a1 = *(const uint32_t*)&sm[(arow + 8) * AP + k0];
        uint32_t a2 = *(const uint32_t*)&sm[arow * AP + k0 + 8];
        uint32_t a3 = *(const uint32_t*)&sm[(arow + 8) * AP + k0 + 8];
        #pragma unroll
        for (int jj = 0; jj < 8; jj++) {
            uint2 b = Wf[((wn * 8 + jj) * 8 + s) * 32 + lane];
            mma16(acc[jj], a0, a1, a2, a3, b.x, b.y);
        }
    }

    int r1 = row0 + wm * 16 + g, r2 = r1 + 8;
    #pragma unroll
    for (int j = 0; j < 8; j++) {
        int col = wn * 64 + j * 8 + ck * 2;
        if (r1 < N_NODES)
            *(__half2*)&g_h[r1 * 128 + col] = __floats2half2_rn(acc[j][0], acc[j][1]);
        if (r2 < N_NODES)
            *(__half2*)&g_h[r2 * 128 + col] = __floats2half2_rn(acc[j][2], acc[j][3]);
    }
}

// GEMM1: A = X (fp32 in gmem) converted to fp16 in smem
__global__ void __launch_bounds__(256) gemm1_k(const float* __restrict__ X,
                                               const uint2* __restrict__ Wf) {
    __shared__ __half sm[64 * AP];
    int row0 = blockIdx.x * 64;
    int tid = threadIdx.x;
    for (int i = tid; i < 64 * 32; i += 256) {
        int r = i >> 5, c4 = i & 31;
        int row = row0 + r;
        float4 v = make_float4(0.f, 0.f, 0.f, 0.f);
        if (row < N_NODES) v = ((const float4*)X)[row * 32 + c4];
        __half2 h0 = __floats2half2_rn(v.x, v.y);
        __half2 h1 = __floats2half2_rn(v.z, v.w);
        uint2 o;
        o.x = *(unsigned*)&h0;
        o.y = *(unsigned*)&h1;
        *(uint2*)&sm[r * AP + c4 * 4] = o;
    }
    __syncthreads();
    gemm_main(sm, Wf, row0, tid);
}

// GEMM2: A = g_act (fp16 in gmem), straight copy into smem
__global__ void __launch_bounds__(256) gemm2_k(const uint2* __restrict__ Wf) {
    __shared__ __half sm[64 * AP];
    int row0 = blockIdx.x * 64;
    int tid = threadIdx.x;
    for (int i = tid; i < 64 * 16; i += 256) {
        int r = i >> 4, c8 = i & 15;
        int row = row0 + r;
        uint4 v = make_uint4(0u, 0u, 0u, 0u);
        if (row < N_NODES) v = ((const uint4*)g_act)[row * 16 + c8];
        *(uint4*)&sm[r * AP + c8 * 8] = v;
    }
    __syncthreads();
    gemm_main(sm, Wf, row0, tid);
}

// ---------------- pull aggregate + bias + relu (warp per node) -----------------
__global__ void __launch_bounds__(256) agg_k(const float* __restrict__ bias) {
    int warp = (blockIdx.x * 256 + threadIdx.x) >> 5;
    int lane = threadIdx.x & 31;
    if (warp >= N_NODES) return;
    int node = warp;
    const uint2* H = (const uint2*)g_h;
    float di = g_dinv[node];
    float sw = di * di;
    float4 self = h2f4(H[node * 32 + lane]);
    float4 acc = make_float4(self.x * sw, self.y * sw, self.z * sw, self.w * sw);

    int m = g_cnt[node];
    if (m > BUCKET) m = BUCKET;
    int base = node * BUCKET;
    for (int c0 = 0; c0 < m; c0 += 32) {
        int rem = m - c0;
        int iters = rem < 32 ? rem : 32;
        int idx = 0;
        float w = 0.f;
        if (lane < iters) {
            idx = g_colsrc[base + c0 + lane];
            w = g_dinv[idx] * di;
        }
        for (int t = 0; t < iters; t++) {
            int s = __shfl_sync(0xffffffff, idx, t);
            float wt = __shfl_sync(0xffffffff, w, t);
            float4 h = h2f4(H[s * 32 + lane]);
            acc.x += h.x * wt;
            acc.y += h.y * wt;
            acc.z += h.z * wt;
            acc.w += h.w * wt;
        }
    }

    float4 b = ((const float4*)bias)[lane];
    acc.x = fmaxf(acc.x + b.x, 0.f);
    acc.y = fmaxf(acc.y + b.y, 0.f);
    acc.z = fmaxf(acc.z + b.z, 0.f);
    acc.w = fmaxf(acc.w + b.w, 0.f);

    __half2 p0 = __floats2half2_rn(acc.x, acc.y);
    __half2 p1 = __floats2half2_rn(acc.z, acc.w);
    uint2 o;
    o.x = *(unsigned*)&p0;
    o.y = *(unsigned*)&p1;
    ((uint2*)g_act)[node * 32 + lane] = o;
}

// ---------------- fused range pool + head --------------------------------------
// One block per graph: nodes [start[g], start[g+1]) (batch sorted). No atomics.
__global__ void __launch_bounds__(128) pool_k(const float* __restrict__ Wlin,
                                              const float* __restrict__ blin,
                                              float* __restrict__ out) {
    __shared__ float s0[128], s1[128];
    int g = blockIdx.x, t = threadIdx.x;
    int beg = g_start[g], end = g_start[g + 1];
    float sum = 0.f;
    for (int n = beg; n < end; n++)
        sum += __half2float(g_act[n * 128 + t]);
    float c = fmaxf((float)(end - beg), 1.0f);
    float p = sum / c;
    s0[t] = p * Wlin[t * 2 + 0];
    s1[t] = p * Wlin[t * 2 + 1];
    __syncthreads();
    for (int off = 64; off; off >>= 1) {
        if (t < off) { s0[t] += s0[t + off]; s1[t] += s1[t + off]; }
        __syncthreads();
    }
    if (t == 0) {
        out[g * 2 + 0] = s0[0] + blin[0];
        out[g * 2 + 1] = s1[0] + blin[1];
    }
}

// ---------------- launch -------------------------------------------------------
extern "C" void kernel_launch(void* const* d_in, const int* in_sizes, int n_in,
                              void* d_out, int out_size) {
    const float* x     = (const float*)d_in[0];
    const int*   ei    = (const int*)d_in[1];
    const int*   batch = (const int*)d_in[2];
    const float* W1    = (const float*)d_in[3];
    const float* b1    = (const float*)d_in[4];
    const float* W2    = (const float*)d_in[5];
    const float* b2    = (const float*)d_in[6];
    const float* Wlin  = (const float*)d_in[7];
    const float* blin  = (const float*)d_in[8];
    float* out = (float*)d_out;

    const int4* src4 = (const int4*)ei;
    const int4* dst4 = (const int4*)(ei + N_EDGES);

    static uint2* s_wf1 = nullptr;
    static uint2* s_wf2 = nullptr;
    static cudaStream_t s2 = nullptr;
    static cudaEvent_t evFork = nullptr, evJoin = nullptr;
    if (!s_wf1) {
        cudaGetSymbolAddress((void**)&s_wf1, g_Wf1);
        cudaGetSymbolAddress((void**)&s_wf2, g_Wf2);
        cudaStreamCreateWithFlags(&s2, cudaStreamNonBlocking);
        cudaEventCreateWithFlags(&evFork, cudaEventDisableTiming);
        cudaEventCreateWithFlags(&evJoin, cudaEventDisableTiming);
    }

    // ---- fork: graph prep on s2, wpack+gemm1 on main ----
    cudaEventRecord(evFork, 0);
    cudaStreamWaitEvent(s2, evFork, 0);

    int zero_total = N_NODES + N_GRAPHS + 1;
    zero_k<<<(zero_total + 255) / 256, 256, 0, s2>>>();
    fill_k<<<(N_EDGES / 4 + 255) / 256, 256, 0, s2>>>(src4, dst4);
    dinv_k<<<(N_NODES + 255) / 256, 256, 0, s2>>>(batch);
    suffix_k<<<1, 1, 0, s2>>>();
    cudaEventRecord(evJoin, s2);

    int gemm_blocks = (N_NODES + 63) / 64;
    wpack_k<<<32, 256>>>(W1, W2);
    gemm1_k<<<gemm_blocks, 256>>>(x, s_wf1);

    cudaStreamWaitEvent(0, evJoin, 0);   // join: agg1 needs CSR + dinv + gemm1

    int agg_blocks = (N_NODES * 32 + 255) / 256;
    agg_k<<<agg_blocks, 256>>>(b1);
    gemm2_k<<<gemm_blocks, 256>>>(s_wf2);
    agg_k<<<agg_blocks, 256>>>(b2);

    pool_k<<<N_GRAPHS, 128>>>(Wlin, blin, out);
}